// round 1
// baseline (speedup 1.0000x reference)
#include <cuda_runtime.h>

#define TPB   128        // threads per block; each owns 12 floats of a 1536-float row
#define BAND  32         // output rows per block
#define HH    384
#define WW    512
#define ROWF  1536       // W * C floats per row
#define NB    (HH / BAND)

static __device__ __forceinline__ int hrefl(int h) {
    // reflect-101: valid for -383 < h < 767 (we only use [-2, 386])
    h = (h < 0) ? -h : h;
    return (h >= HH) ? (2 * HH - 2 - h) : h;
}

__global__ void __launch_bounds__(TPB)
gauss5_kernel(const float* __restrict__ x, float* __restrict__ y)
{
    // Gaussian taps for ksize=5, sigma=1.1 (OpenCV default), normalized.
    constexpr float c0 = 0.07076630f;   // w[0] = w[4]
    constexpr float c1 = 0.24446028f;   // w[1] = w[3]
    constexpr float c2 = 0.36954642f;   // w[2]

    const int t  = threadIdx.x;
    const int h0 = blockIdx.x * BAND;
    const long img = blockIdx.y;

    const float* __restrict__ base  = x + img * (long)(HH * ROWF) + t * 12;
    float*       __restrict__ obase = y + img * (long)(HH * ROWF) + t * 12;

    // Double-buffered staging of the vertically-blurred row (3 float4 per thread).
    __shared__ float4 sbuf[2][TPB][3];

    // 5-row sliding window, 12 floats per row, in registers.
    float rw[5][12];
    #pragma unroll
    for (int q = 0; q < 5; q++) {
        const float4* p = (const float4*)(base + (long)hrefl(h0 + q - 2) * ROWF);
        float4 a = p[0], b = p[1], c = p[2];
        rw[q][0]=a.x; rw[q][1]=a.y; rw[q][2]=a.z; rw[q][3]=a.w;
        rw[q][4]=b.x; rw[q][5]=b.y; rw[q][6]=b.z; rw[q][7]=b.w;
        rw[q][8]=c.x; rw[q][9]=c.y; rw[q][10]=c.z; rw[q][11]=c.w;
    }

    #pragma unroll 5
    for (int r = 0; r < BAND; r++) {
        // Prefetch the next input row (window bottom for iteration r+1).
        const float4* p = (const float4*)(base + (long)hrefl(h0 + r + 3) * ROWF);
        float4 na = p[0], nb = p[1], nc = p[2];

        // Vertical pass (symmetric taps), registers only.
        float sv[12];
        #pragma unroll
        for (int j = 0; j < 12; j++)
            sv[j] = c0 * (rw[0][j] + rw[4][j])
                  + c1 * (rw[1][j] + rw[3][j])
                  + c2 *  rw[2][j];

        const int pb = r & 1;
        sbuf[pb][t][0] = make_float4(sv[0], sv[1], sv[2],  sv[3]);
        sbuf[pb][t][1] = make_float4(sv[4], sv[5], sv[6],  sv[7]);
        sbuf[pb][t][2] = make_float4(sv[8], sv[9], sv[10], sv[11]);
        __syncthreads();

        // Extended 24-float window: e[j] = sv_flat(12*t - 6 + j)
        float e[24];
        #pragma unroll
        for (int j = 0; j < 12; j++) e[6 + j] = sv[j];

        if (t > 0) {
            float4 L1 = sbuf[pb][t - 1][1];
            float4 L2 = sbuf[pb][t - 1][2];
            e[0] = L1.z; e[1] = L1.w; e[2] = L2.x;
            e[3] = L2.y; e[4] = L2.z; e[5] = L2.w;
        } else {
            // w = -2 -> 2 (flats 6..8), w = -1 -> 1 (flats 3..5)
            e[0] = sv[6]; e[1] = sv[7]; e[2] = sv[8];
            e[3] = sv[3]; e[4] = sv[4]; e[5] = sv[5];
        }
        if (t < TPB - 1) {
            float4 R0 = sbuf[pb][t + 1][0];
            float4 R1 = sbuf[pb][t + 1][1];
            e[18] = R0.x; e[19] = R0.y; e[20] = R0.z;
            e[21] = R0.w; e[22] = R1.x; e[23] = R1.y;
        } else {
            // w = 512 -> 510 (local flats 6..8), w = 513 -> 509 (local flats 3..5)
            e[18] = sv[6]; e[19] = sv[7]; e[20] = sv[8];
            e[21] = sv[3]; e[22] = sv[4]; e[23] = sv[5];
        }

        // Horizontal pass: taps at flat offsets {-6,-3,0,+3,+6}.
        float o[12];
        #pragma unroll
        for (int i = 0; i < 12; i++)
            o[i] = c0 * (e[i]     + e[i + 12])
                 + c1 * (e[i + 3] + e[i + 9])
                 + c2 *  e[i + 6];

        float4* op = (float4*)(obase + (long)(h0 + r) * ROWF);
        op[0] = make_float4(o[0], o[1], o[2],  o[3]);
        op[1] = make_float4(o[4], o[5], o[6],  o[7]);
        op[2] = make_float4(o[8], o[9], o[10], o[11]);

        // Slide the window down one row.
        #pragma unroll
        for (int q = 0; q < 4; q++) {
            #pragma unroll
            for (int j = 0; j < 12; j++) rw[q][j] = rw[q + 1][j];
        }
        rw[4][0]=na.x; rw[4][1]=na.y; rw[4][2]=na.z; rw[4][3]=na.w;
        rw[4][4]=nb.x; rw[4][5]=nb.y; rw[4][6]=nb.z; rw[4][7]=nb.w;
        rw[4][8]=nc.x; rw[4][9]=nc.y; rw[4][10]=nc.z; rw[4][11]=nc.w;
    }
}

extern "C" void kernel_launch(void* const* d_in, const int* in_sizes, int n_in,
                              void* d_out, int out_size)
{
    const float* x = (const float*)d_in[0];
    float* y = (float*)d_out;
    const int batch = in_sizes[0] / (HH * ROWF);   // 64
    dim3 grid(NB, batch);
    gauss5_kernel<<<grid, TPB>>>(x, y);
}

// round 2
// speedup vs baseline: 1.0917x; 1.0917x over previous
#include <cuda_runtime.h>

#define TPB   384        // one thread per float4 of a 1536-float row
#define BAND  16         // output rows per block
#define HH    384
#define ROWF  1536       // W * C floats per row
#define ROW4  (ROWF / 4)
#define NB    (HH / BAND)

static __device__ __forceinline__ int hrefl(int h) {
    // reflect-101 along height; only used for h in [-2, HH+2]
    h = (h < 0) ? -h : h;
    return (h >= HH) ? (2 * HH - 2 - h) : h;
}

// reflect-101 on the flat (w*3+c) index along width (W=512, flats [0,1536))
static __device__ __forceinline__ int frefl(int f) {
    if (f < 0) {
        int w = f / 3, c = f - 3 * w;
        if (c < 0) { w -= 1; c += 3; }
        return 3 * (-w) + c;
    }
    if (f >= ROWF) {
        int w = f / 3, c = f - 3 * w;
        return 3 * (1022 - w) + c;     // 2*(512-1) - w
    }
    return f;
}

__global__ void __launch_bounds__(TPB, 3)
gauss5_kernel(const float* __restrict__ x, float* __restrict__ y)
{
    // Gaussian taps for ksize=5, sigma=1.1 (OpenCV default), normalized.
    constexpr float c0 = 0.07076630f;   // w[0] = w[4]
    constexpr float c1 = 0.24446028f;   // w[1] = w[3]
    constexpr float c2 = 0.36954642f;   // w[2]

    const int t  = threadIdx.x;
    const int h0 = blockIdx.x * BAND;
    const long img = blockIdx.y;

    const float4* __restrict__ bin  = (const float4*)(x + img * (long)(HH * ROWF)) + t;
    float4*       __restrict__ bout = (float4*)      (y + img * (long)(HH * ROWF)) + t;

    // Double-buffered vertically-blurred row (1536 floats = 6 KB each).
    __shared__ float sb[2][ROWF];

    // 5-row sliding window, one float4 per row, in registers.
    float4 rw[5];
    #pragma unroll
    for (int q = 0; q < 5; q++)
        rw[q] = bin[(long)hrefl(h0 + q - 2) * ROW4];

    #pragma unroll 4
    for (int r = 0; r < BAND; r++) {
        // Prefetch next input row early (consumed at the window slide below).
        float4 nxt = bin[(long)hrefl(h0 + r + 3) * ROW4];

        // Vertical pass (symmetric taps), registers only.
        float4 sv;
        sv.x = c0 * (rw[0].x + rw[4].x) + c1 * (rw[1].x + rw[3].x) + c2 * rw[2].x;
        sv.y = c0 * (rw[0].y + rw[4].y) + c1 * (rw[1].y + rw[3].y) + c2 * rw[2].y;
        sv.z = c0 * (rw[0].z + rw[4].z) + c1 * (rw[1].z + rw[3].z) + c2 * rw[2].z;
        sv.w = c0 * (rw[0].w + rw[4].w) + c1 * (rw[1].w + rw[3].w) + c2 * rw[2].w;

        const int pb = r & 1;
        ((float4*)sb[pb])[t] = sv;
        __syncthreads();

        // Horizontal halo: flats [4t-6, 4t-1] (L) and [4t+4, 4t+9] (R).
        float L[6], R[6];
        if (t >= 2 && t < TPB - 2) {
            float4 A = ((const float4*)sb[pb])[t - 2];
            float4 B = ((const float4*)sb[pb])[t - 1];
            float4 C = ((const float4*)sb[pb])[t + 1];
            float4 D = ((const float4*)sb[pb])[t + 2];
            L[0] = A.z; L[1] = A.w; L[2] = B.x; L[3] = B.y; L[4] = B.z; L[5] = B.w;
            R[0] = C.x; R[1] = C.y; R[2] = C.z; R[3] = C.w; R[4] = D.x; R[5] = D.y;
        } else {
            #pragma unroll
            for (int j = 0; j < 6; j++) {
                L[j] = sb[pb][frefl(4 * t - 6 + j)];
                R[j] = sb[pb][frefl(4 * t + 4 + j)];
            }
        }

        // Extended window e[j] = sv_flat(4t - 6 + j), j = 0..15.
        float e[16];
        e[0] = L[0]; e[1] = L[1]; e[2]  = L[2]; e[3]  = L[3]; e[4]  = L[4]; e[5]  = L[5];
        e[6] = sv.x; e[7] = sv.y; e[8]  = sv.z; e[9]  = sv.w;
        e[10] = R[0]; e[11] = R[1]; e[12] = R[2]; e[13] = R[3]; e[14] = R[4]; e[15] = R[5];

        // Horizontal pass: taps at flat offsets {-6,-3,0,+3,+6}.
        float4 o;
        o.x = c0 * (e[0] + e[12]) + c1 * (e[3] + e[9])  + c2 * e[6];
        o.y = c0 * (e[1] + e[13]) + c1 * (e[4] + e[10]) + c2 * e[7];
        o.z = c0 * (e[2] + e[14]) + c1 * (e[5] + e[11]) + c2 * e[8];
        o.w = c0 * (e[3] + e[15]) + c1 * (e[6] + e[12]) + c2 * e[9];

        bout[(long)(h0 + r) * ROW4] = o;

        // Slide the window down one row.
        rw[0] = rw[1]; rw[1] = rw[2]; rw[2] = rw[3]; rw[3] = rw[4]; rw[4] = nxt;
    }
}

extern "C" void kernel_launch(void* const* d_in, const int* in_sizes, int n_in,
                              void* d_out, int out_size)
{
    const float* x = (const float*)d_in[0];
    float* y = (float*)d_out;
    const int batch = in_sizes[0] / (HH * ROWF);   // 64
    dim3 grid(NB, batch);
    gauss5_kernel<<<grid, TPB>>>(x, y);
}